// round 10
// baseline (speedup 1.0000x reference)
#include <cuda_runtime.h>
#include <cuda_bf16.h>

// Problem: feature [N, C] fp32, label [N] int32.
// loss = 2 - 2*(sum_i feature[i, label[i]] / 64) / N  = 2 - sum / (32*N)
//
// Single kernel, NO smem / NO __syncthreads: each warp reduces its 32 gathered
// values via shfl, then lane 0 adds one packed 64-bit term to a global
// accumulator:
//   bits [53:64) : warp-arrival count (256 warps -> fits in 11 bits)
//   bits [0:53)  : sum of (warp_sum * 2^32 + 2^44)  (bias keeps terms
//                  positive; 256 biased terms < 2^53 -> fields never collide)
// The warp that sees count==255 in the RETURN VALUE already holds the sum of
// all other 255 partials -> finalizes immediately. Fixed-point accumulation is
// order-independent -> bit-exact deterministic across replays. Last warp
// resets the accumulator -> graph-replayable.

#define TPB 256

__device__ unsigned long long g_accum = 0;

__global__ void __launch_bounds__(TPB, 1) center_fused(
        const float* __restrict__ feature,
        const int* __restrict__ label,
        int n, int c, float inv_denom,
        float* __restrict__ out) {
    int i = blockIdx.x * TPB + threadIdx.x;
    float v = 0.0f;
    if (i < n) {
        int col = label[i];
        v = __ldg(&feature[(long long)i * c + col]);
    }

    // warp reduce (32 values -> 1)
    #pragma unroll
    for (int off = 16; off > 0; off >>= 1)
        v += __shfl_xor_sync(0xFFFFFFFFu, v, off);

    if ((threadIdx.x & 31) == 0) {
        // fixed-point term: v * 2^32, biased by 2^44 (|v| < 2^8 -> |fixed| < 2^40)
        long long fixed = __double2ll_rn((double)v * 4294967296.0);
        unsigned long long term =
            (1ULL << 53) + (unsigned long long)(fixed + (1LL << 44));
        unsigned long long old = atomicAdd(&g_accum, term);

        unsigned int nwarps = gridDim.x * (TPB / 32);   // 256
        if ((old >> 53) == (unsigned long long)(nwarps - 1)) {
            const unsigned long long M = (1ULL << 53) - 1;
            long long total =
                (long long)((old & M) +
                            (unsigned long long)(fixed + (1LL << 44))) -
                ((long long)nwarps << 44);
            double sum = (double)total * (1.0 / 4294967296.0);
            out[0] = 2.0f - (float)sum * inv_denom;
            g_accum = 0;  // reset for next graph replay
        }
    }
}

extern "C" void kernel_launch(void* const* d_in, const int* in_sizes, int n_in,
                              void* d_out, int out_size) {
    const float* feature = (const float*)d_in[0];
    const int*   label   = (const int*)d_in[1];
    float*       out     = (float*)d_out;

    int n = in_sizes[1];              // 8192
    int c = (int)(in_sizes[0] / n);   // 10000

    int nblocks = (n + TPB - 1) / TPB;   // 32

    float inv_denom = 1.0f / (32.0f * (float)n);

    center_fused<<<nblocks, TPB>>>(feature, label, n, c, inv_denom, out);
}